// round 1
// baseline (speedup 1.0000x reference)
#include <cuda_runtime.h>
#include <cstdint>
#include <cstddef>

#define Gn   32
#define NN   1200
#define EE   19200
#define SUMH 1024

// ---------------- static scratch (no cudaMalloc allowed) ----------------
__device__ float g_hcat[(size_t)Gn * NN * SUMH];   // concat(h1..h4), conv input
__device__ float g_A[(size_t)Gn * NN * 256];       // aggregated features per layer
__device__ int   g_rowptr[Gn * (NN + 1)];
__device__ int   g_esrc[Gn * EE];
__device__ float g_sout[Gn * NN];
__device__ float g_sin[Gn * NN];

// ---------------- CSR build + degree scales (one CTA per graph) ----------------
__global__ void build_csr_kernel(const int* __restrict__ src, const int* __restrict__ dst) {
    __shared__ int s_in[NN];
    __shared__ int s_out[NN];
    __shared__ int s_ptr[NN + 1];
    int g = blockIdx.x, t = threadIdx.x;
    for (int i = t; i < NN; i += blockDim.x) { s_in[i] = 0; s_out[i] = 0; }
    __syncthreads();
    const int* sg = src + g * EE;
    const int* dg = dst + g * EE;
    for (int e = t; e < EE; e += blockDim.x) {
        atomicAdd(&s_out[sg[e]], 1);
        atomicAdd(&s_in[dg[e]], 1);
    }
    __syncthreads();
    for (int i = t; i < NN; i += blockDim.x) {
        int od = s_out[i] < 1 ? 1 : s_out[i];
        int id = s_in[i]  < 1 ? 1 : s_in[i];
        g_sout[g * NN + i] = rsqrtf((float)od);
        g_sin[g * NN + i]  = rsqrtf((float)id);
    }
    if (t == 0) {
        int run = 0;
        for (int i = 0; i < NN; i++) { s_ptr[i] = run; run += s_in[i]; }
        s_ptr[NN] = run;
    }
    __syncthreads();
    for (int i = t; i <= NN; i += blockDim.x) g_rowptr[g * (NN + 1) + i] = s_ptr[i];
    for (int i = t; i < NN; i += blockDim.x) s_in[i] = s_ptr[i];   // write cursors
    __syncthreads();
    for (int e = t; e < EE; e += blockDim.x) {
        int d = dg[e];
        int pos = atomicAdd(&s_in[d], 1);
        g_esrc[g * EE + pos] = sg[e];
    }
}

// ---------------- SpMM: A[v] = s_in[v] * sum_{e: dst=v} h[src_e] * s_out[src_e] ----------------
// One CTA per (node, graph); D threads, thread = feature.
template <int D, bool FROM_HCAT>
__global__ void spmm_kernel(const float* __restrict__ hext, int col_off) {
    int v = blockIdx.x, g = blockIdx.y, f = threadIdx.x;
    const int* rp = g_rowptr + g * (NN + 1);
    int beg = rp[v], end = rp[v + 1];
    const int* es = g_esrc + g * EE;
    float acc = 0.f;
    #pragma unroll 4
    for (int e = beg; e < end; e++) {
        int s = es[e];
        float sc = g_sout[g * NN + s];
        float hv;
        if (FROM_HCAT) hv = g_hcat[((size_t)g * NN + s) * SUMH + col_off + f];
        else           hv = hext[((size_t)g * NN + s) * D + f];
        acc += hv * sc;
    }
    g_A[((size_t)g * NN + v) * D + f] = acc * g_sin[g * NN + v];
}

// ---------------- GEMM + bias + ReLU: h = relu(A(1200xK) @ W(Kx256) + b) -> g_hcat cols ----------------
// 128x128 CTA tile, BK=16, 256 threads, 8x8 microtile.
template <int K>
__global__ __launch_bounds__(256) void gemm_kernel(const float* __restrict__ W,
                                                   const float* __restrict__ bias,
                                                   int col_off) {
    __shared__ float As[16][132];
    __shared__ float Bs[16][132];
    int g = blockIdx.z;
    int m0 = blockIdx.x * 128, n0 = blockIdx.y * 128;
    int tid = threadIdx.x;
    int tx = tid & 15, ty = tid >> 4;

    float acc[8][8];
    #pragma unroll
    for (int i = 0; i < 8; i++)
        #pragma unroll
        for (int j = 0; j < 8; j++) acc[i][j] = 0.f;

    int arow = tid >> 1;          // 0..127
    int acol = (tid & 1) * 8;     // 0 or 8
    int brow = tid >> 4;          // 0..15
    int bcol = (tid & 15) * 8;    // 0..120

    const float* Ag = g_A + (size_t)g * NN * K;
    bool a_ok = (m0 + arow) < NN;
    const float* aptr = Ag + (size_t)(m0 + arow) * K + acol;
    const float* bptr = W + (size_t)brow * 256 + n0 + bcol;

    for (int k0 = 0; k0 < K; k0 += 16) {
        float4 a0, a1;
        if (a_ok) {
            a0 = *(const float4*)(aptr + k0);
            a1 = *(const float4*)(aptr + k0 + 4);
        } else {
            a0 = make_float4(0.f, 0.f, 0.f, 0.f);
            a1 = a0;
        }
        float4 b0 = *(const float4*)(bptr + (size_t)k0 * 256);
        float4 b1 = *(const float4*)(bptr + (size_t)k0 * 256 + 4);
        __syncthreads();
        As[acol + 0][arow] = a0.x; As[acol + 1][arow] = a0.y;
        As[acol + 2][arow] = a0.z; As[acol + 3][arow] = a0.w;
        As[acol + 4][arow] = a1.x; As[acol + 5][arow] = a1.y;
        As[acol + 6][arow] = a1.z; As[acol + 7][arow] = a1.w;
        *(float4*)&Bs[brow][bcol]     = b0;
        *(float4*)&Bs[brow][bcol + 4] = b1;
        __syncthreads();
        #pragma unroll
        for (int k = 0; k < 16; k++) {
            float af[8], bf[8];
            #pragma unroll
            for (int i = 0; i < 8; i++) af[i] = As[k][ty + 16 * i];
            #pragma unroll
            for (int j = 0; j < 8; j++) bf[j] = Bs[k][tx + 16 * j];
            #pragma unroll
            for (int i = 0; i < 8; i++)
                #pragma unroll
                for (int j = 0; j < 8; j++) acc[i][j] += af[i] * bf[j];
        }
    }

    float bv[8];
    #pragma unroll
    for (int j = 0; j < 8; j++) bv[j] = bias[n0 + tx + 16 * j];
    #pragma unroll
    for (int i = 0; i < 8; i++) {
        int m = m0 + ty + 16 * i;
        if (m < NN) {
            float* orow = g_hcat + ((size_t)g * NN + m) * SUMH + col_off;
            #pragma unroll
            for (int j = 0; j < 8; j++) {
                float v = acc[i][j] + bv[j];
                orow[n0 + tx + 16 * j] = v > 0.f ? v : 0.f;
            }
        }
    }
}

// ---------------- fused 13x13 conv (1->3 ch) + max-pool over 40-row blocks ----------------
// CTA = (col tile of 128, pool block of 40 rows, graph). 256 thr = 128 cols x 2 row-halves.
__global__ __launch_bounds__(256) void conv_pool_kernel(const float* __restrict__ cw,
                                                        const float* __restrict__ cb,
                                                        float* __restrict__ out) {
    __shared__ float s_img[52][140];
    __shared__ float s_w[507];
    int ct = blockIdx.x, p = blockIdx.y, g = blockIdx.z;
    int tid = threadIdx.x;
    for (int i = tid; i < 507; i += 256) s_w[i] = cw[i];

    int base_r = p * 40 - 6, base_c = ct * 128 - 6;
    const float* hg = g_hcat + (size_t)g * NN * SUMH;
    for (int idx = tid; idx < 52 * 140; idx += 256) {
        int r = idx / 140, c = idx - r * 140;
        int gr = base_r + r, gc = base_c + c;
        float v = 0.f;
        if (gr >= 0 && gr < NN && gc >= 0 && gc < SUMH)
            v = hg[(size_t)gr * SUMH + gc];
        s_img[r][c] = v;
    }
    __syncthreads();

    int tx = tid & 127, ty = tid >> 7;
    float mx0 = -1e30f, mx1 = -1e30f, mx2 = -1e30f;

    #pragma unroll
    for (int chunk = 0; chunk < 2; chunk++) {
        float acc0[10], acc1[10], acc2[10];
        #pragma unroll
        for (int t = 0; t < 10; t++) { acc0[t] = 0.f; acc1[t] = 0.f; acc2[t] = 0.f; }
        int rbase = ty * 20 + chunk * 10;   // local output row base
        #pragma unroll 1
        for (int kc = 0; kc < 13; kc++) {
            float v[22];
            #pragma unroll
            for (int i = 0; i < 22; i++) v[i] = s_img[rbase + i][tx + kc];
            #pragma unroll
            for (int kr = 0; kr < 13; kr++) {
                float w0 = s_w[kr * 13 + kc];
                float w1 = s_w[169 + kr * 13 + kc];
                float w2 = s_w[338 + kr * 13 + kc];
                #pragma unroll
                for (int t = 0; t < 10; t++) {
                    float x = v[kr + t];
                    acc0[t] += x * w0;
                    acc1[t] += x * w1;
                    acc2[t] += x * w2;
                }
            }
        }
        #pragma unroll
        for (int t = 0; t < 10; t++) {
            mx0 = fmaxf(mx0, acc0[t]);
            mx1 = fmaxf(mx1, acc1[t]);
            mx2 = fmaxf(mx2, acc2[t]);
        }
    }

    __syncthreads();                 // done reading s_img; reuse for reduction
    float* red = &s_img[0][0];
    if (ty == 1) { red[tx] = mx0; red[128 + tx] = mx1; red[256 + tx] = mx2; }
    __syncthreads();
    if (ty == 0) {
        mx0 = fmaxf(mx0, red[tx]);
        mx1 = fmaxf(mx1, red[128 + tx]);
        mx2 = fmaxf(mx2, red[256 + tx]);
        int c = ct * 128 + tx;
        out[((size_t)(g * 3 + 0) * 30 + p) * SUMH + c] = mx0 + cb[0];
        out[((size_t)(g * 3 + 1) * 30 + p) * SUMH + c] = mx1 + cb[1];
        out[((size_t)(g * 3 + 2) * 30 + p) * SUMH + c] = mx2 + cb[2];
    }
}

// ---------------- driver ----------------
extern "C" void kernel_launch(void* const* d_in, const int* in_sizes, int n_in,
                              void* d_out, int out_size) {
    const float* feat = (const float*)d_in[0];
    const int*   src  = (const int*)d_in[1];
    const int*   dst  = (const int*)d_in[2];
    const float* W1 = (const float*)d_in[3];  const float* b1 = (const float*)d_in[4];
    const float* W2 = (const float*)d_in[5];  const float* b2 = (const float*)d_in[6];
    const float* W3 = (const float*)d_in[7];  const float* b3 = (const float*)d_in[8];
    const float* W4 = (const float*)d_in[9];  const float* b4 = (const float*)d_in[10];
    const float* cw = (const float*)d_in[11]; const float* cb = (const float*)d_in[12];
    float* out = (float*)d_out;

    build_csr_kernel<<<Gn, 256>>>(src, dst);

    // layer 1: input = features (K=128)
    spmm_kernel<128, false><<<dim3(NN, Gn), 128>>>(feat, 0);
    gemm_kernel<128><<<dim3(10, 2, Gn), 256>>>(W1, b1, 0);
    // layer 2
    spmm_kernel<256, true><<<dim3(NN, Gn), 256>>>(nullptr, 0);
    gemm_kernel<256><<<dim3(10, 2, Gn), 256>>>(W2, b2, 256);
    // layer 3
    spmm_kernel<256, true><<<dim3(NN, Gn), 256>>>(nullptr, 256);
    gemm_kernel<256><<<dim3(10, 2, Gn), 256>>>(W3, b3, 512);
    // layer 4
    spmm_kernel<256, true><<<dim3(NN, Gn), 256>>>(nullptr, 512);
    gemm_kernel<256><<<dim3(10, 2, Gn), 256>>>(W4, b4, 768);

    conv_pool_kernel<<<dim3(8, 30, Gn), 256>>>(cw, cb, out);
}

// round 2
// speedup vs baseline: 1.1266x; 1.1266x over previous
#include <cuda_runtime.h>
#include <cstdint>
#include <cstddef>

#define Gn   32
#define NN   1200
#define EE   19200
#define SUMH 1024

// ---------------- static scratch (no cudaMalloc allowed) ----------------
__device__ float g_hcat[(size_t)Gn * NN * SUMH];   // concat(h1..h4), conv input
__device__ float g_A[(size_t)Gn * NN * 256];       // aggregated features per layer
__device__ int   g_rowptr[Gn * (NN + 1)];
__device__ int   g_esrc[Gn * EE];
__device__ float g_esc[Gn * EE];                   // per-edge s_out scale (kills dependent gather)
__device__ float g_sin[Gn * NN];

// ---------------- CSR build + degree scales (one CTA per graph) ----------------
__global__ void build_csr_kernel(const int* __restrict__ src, const int* __restrict__ dst) {
    __shared__ int s_in[NN];
    __shared__ int s_out[NN];
    __shared__ int s_ptr[NN + 1];
    int g = blockIdx.x, t = threadIdx.x;
    for (int i = t; i < NN; i += blockDim.x) { s_in[i] = 0; s_out[i] = 0; }
    __syncthreads();
    const int* sg = src + g * EE;
    const int* dg = dst + g * EE;
    for (int e = t; e < EE; e += blockDim.x) {
        atomicAdd(&s_out[sg[e]], 1);
        atomicAdd(&s_in[dg[e]], 1);
    }
    __syncthreads();
    for (int i = t; i < NN; i += blockDim.x) {
        int id = s_in[i] < 1 ? 1 : s_in[i];
        g_sin[g * NN + i] = rsqrtf((float)id);
    }
    if (t == 0) {
        int run = 0;
        for (int i = 0; i < NN; i++) { s_ptr[i] = run; run += s_in[i]; }
        s_ptr[NN] = run;
    }
    __syncthreads();
    for (int i = t; i <= NN; i += blockDim.x) g_rowptr[g * (NN + 1) + i] = s_ptr[i];
    for (int i = t; i < NN; i += blockDim.x) s_in[i] = s_ptr[i];   // write cursors
    __syncthreads();
    for (int e = t; e < EE; e += blockDim.x) {
        int d = dg[e];
        int s = sg[e];
        int pos = atomicAdd(&s_in[d], 1);
        int od = s_out[s] < 1 ? 1 : s_out[s];
        g_esrc[g * EE + pos] = s;
        g_esc[g * EE + pos]  = rsqrtf((float)od);
    }
}

// ---------------- SpMM: A[v] = s_in[v] * sum_{e: dst=v} h[src_e] * s_out[src_e] ----------------
// 256 threads/CTA, float4 per thread, multiple nodes per CTA.
template <int D, bool FROM_HCAT>
__global__ __launch_bounds__(256) void spmm_kernel(const float* __restrict__ hext, int col_off) {
    constexpr int LPN = D / 4;          // threads per node
    constexpr int NPB = 256 / LPN;      // nodes per CTA
    int g = blockIdx.y;
    int lane = threadIdx.x & (LPN - 1);
    int ni   = threadIdx.x / LPN;
    int v = blockIdx.x * NPB + ni;

    const int* rp = g_rowptr + g * (NN + 1);
    int beg = rp[v], end = rp[v + 1];
    const int*   es  = g_esrc + g * EE;
    const float* esc = g_esc  + g * EE;

    float4 acc = make_float4(0.f, 0.f, 0.f, 0.f);
    const float* base;
    size_t rstride;
    if (FROM_HCAT) { base = g_hcat + (size_t)g * NN * SUMH + col_off + 4 * lane; rstride = SUMH; }
    else           { base = hext   + (size_t)g * NN * D    + 4 * lane;           rstride = D;    }

    #pragma unroll 4
    for (int e = beg; e < end; e++) {
        int s = es[e];
        float sc = esc[e];
        float4 hv = *(const float4*)(base + (size_t)s * rstride);
        acc.x += hv.x * sc; acc.y += hv.y * sc;
        acc.z += hv.z * sc; acc.w += hv.w * sc;
    }
    float si = g_sin[g * NN + v];
    acc.x *= si; acc.y *= si; acc.z *= si; acc.w *= si;
    *(float4*)(g_A + ((size_t)g * NN + v) * D + 4 * lane) = acc;
}

// ---------------- GEMM + bias + ReLU: h = relu(A(1200xK) @ W(Kx256) + b) -> g_hcat cols ----------------
// 128x128 CTA tile, BK=16, 256 threads, 8x8 microtile, double-buffered smem.
template <int K>
__global__ __launch_bounds__(256) void gemm_kernel(const float* __restrict__ W,
                                                   const float* __restrict__ bias,
                                                   int col_off) {
    __shared__ float As[2][16][132];
    __shared__ float Bs[2][16][132];
    int g = blockIdx.z;
    int m0 = blockIdx.x * 128, n0 = blockIdx.y * 128;
    int tid = threadIdx.x;
    int tx = tid & 15, ty = tid >> 4;

    float acc[8][8];
    #pragma unroll
    for (int i = 0; i < 8; i++)
        #pragma unroll
        for (int j = 0; j < 8; j++) acc[i][j] = 0.f;

    int arow = tid >> 1;          // 0..127
    int acol = (tid & 1) * 8;     // 0 or 8
    int brow = tid >> 4;          // 0..15
    int bcol = (tid & 15) * 8;    // 0..120

    const float* Ag = g_A + (size_t)g * NN * K;
    bool a_ok = (m0 + arow) < NN;
    const float* aptr = Ag + (size_t)(m0 + arow) * K + acol;
    const float* bptr = W + (size_t)brow * 256 + n0 + bcol;

    // preload tile 0 into buffer 0
    {
        float4 a0, a1;
        if (a_ok) { a0 = *(const float4*)(aptr); a1 = *(const float4*)(aptr + 4); }
        else      { a0 = make_float4(0.f,0.f,0.f,0.f); a1 = a0; }
        float4 b0 = *(const float4*)(bptr);
        float4 b1 = *(const float4*)(bptr + 4);
        As[0][acol + 0][arow] = a0.x; As[0][acol + 1][arow] = a0.y;
        As[0][acol + 2][arow] = a0.z; As[0][acol + 3][arow] = a0.w;
        As[0][acol + 4][arow] = a1.x; As[0][acol + 5][arow] = a1.y;
        As[0][acol + 6][arow] = a1.z; As[0][acol + 7][arow] = a1.w;
        *(float4*)&Bs[0][brow][bcol]     = b0;
        *(float4*)&Bs[0][brow][bcol + 4] = b1;
    }
    __syncthreads();

    int buf = 0;
    for (int k0 = 0; k0 < K; k0 += 16) {
        int kn = k0 + 16;
        bool have_next = kn < K;
        float4 a0, a1, b0, b1;
        if (have_next) {
            if (a_ok) { a0 = *(const float4*)(aptr + kn); a1 = *(const float4*)(aptr + kn + 4); }
            else      { a0 = make_float4(0.f,0.f,0.f,0.f); a1 = a0; }
            b0 = *(const float4*)(bptr + (size_t)kn * 256);
            b1 = *(const float4*)(bptr + (size_t)kn * 256 + 4);
        }
        #pragma unroll
        for (int k = 0; k < 16; k++) {
            float af[8], bf[8];
            #pragma unroll
            for (int i = 0; i < 8; i++) af[i] = As[buf][k][ty + 16 * i];
            #pragma unroll
            for (int j = 0; j < 8; j++) bf[j] = Bs[buf][k][tx + 16 * j];
            #pragma unroll
            for (int i = 0; i < 8; i++)
                #pragma unroll
                for (int j = 0; j < 8; j++) acc[i][j] += af[i] * bf[j];
        }
        if (have_next) {
            int nb = buf ^ 1;
            As[nb][acol + 0][arow] = a0.x; As[nb][acol + 1][arow] = a0.y;
            As[nb][acol + 2][arow] = a0.z; As[nb][acol + 3][arow] = a0.w;
            As[nb][acol + 4][arow] = a1.x; As[nb][acol + 5][arow] = a1.y;
            As[nb][acol + 6][arow] = a1.z; As[nb][acol + 7][arow] = a1.w;
            *(float4*)&Bs[nb][brow][bcol]     = b0;
            *(float4*)&Bs[nb][brow][bcol + 4] = b1;
            __syncthreads();
            buf = nb;
        }
    }

    float bv[8];
    #pragma unroll
    for (int j = 0; j < 8; j++) bv[j] = bias[n0 + tx + 16 * j];
    #pragma unroll
    for (int i = 0; i < 8; i++) {
        int m = m0 + ty + 16 * i;
        if (m < NN) {
            float* orow = g_hcat + ((size_t)g * NN + m) * SUMH + col_off;
            #pragma unroll
            for (int j = 0; j < 8; j++) {
                float v = acc[i][j] + bv[j];
                orow[n0 + tx + 16 * j] = v > 0.f ? v : 0.f;
            }
        }
    }
}

// ---------------- fused 13x13 conv (1->3 ch) + max-pool over 40-row blocks ----------------
// CTA = (col tile of 128, pool block of 40 rows, graph). 256 thr = 128 cols x 2 halves (T=20 rows each).
__global__ __launch_bounds__(256) void conv_pool_kernel(const float* __restrict__ cw,
                                                        const float* __restrict__ cb,
                                                        float* __restrict__ out) {
    __shared__ float s_img[52][140];
    __shared__ float s_w[507];
    int ct = blockIdx.x, p = blockIdx.y, g = blockIdx.z;
    int tid = threadIdx.x;
    for (int i = tid; i < 507; i += 256) s_w[i] = cw[i];

    int base_r = p * 40 - 6, base_c = ct * 128 - 6;
    const float* hg = g_hcat + (size_t)g * NN * SUMH;
    for (int idx = tid; idx < 52 * 140; idx += 256) {
        int r = idx / 140, c = idx - r * 140;
        int gr = base_r + r, gc = base_c + c;
        float v = 0.f;
        if (gr >= 0 && gr < NN && gc >= 0 && gc < SUMH)
            v = hg[(size_t)gr * SUMH + gc];
        s_img[r][c] = v;
    }
    __syncthreads();

    int tx = tid & 127, ty = tid >> 7;
    int rbase = ty * 20;                // rows rbase..rbase+19
    float mx0 = -1e30f, mx1 = -1e30f, mx2 = -1e30f;

    {
        float acc0[20], acc1[20], acc2[20];
        #pragma unroll
        for (int t = 0; t < 20; t++) { acc0[t] = 0.f; acc1[t] = 0.f; acc2[t] = 0.f; }
        #pragma unroll 1
        for (int kc = 0; kc < 13; kc++) {
            float v[32];
            #pragma unroll
            for (int i = 0; i < 32; i++) v[i] = s_img[rbase + i][tx + kc];
            #pragma unroll
            for (int kr = 0; kr < 13; kr++) {
                float w0 = s_w[kr * 13 + kc];
                float w1 = s_w[169 + kr * 13 + kc];
                float w2 = s_w[338 + kr * 13 + kc];
                #pragma unroll
                for (int t = 0; t < 20; t++) {
                    float x = v[kr + t];
                    acc0[t] += x * w0;
                    acc1[t] += x * w1;
                    acc2[t] += x * w2;
                }
            }
        }
        #pragma unroll
        for (int t = 0; t < 20; t++) {
            mx0 = fmaxf(mx0, acc0[t]);
            mx1 = fmaxf(mx1, acc1[t]);
            mx2 = fmaxf(mx2, acc2[t]);
        }
    }

    __syncthreads();                 // done reading s_img; reuse for reduction
    float* red = &s_img[0][0];
    if (ty == 1) { red[tx] = mx0; red[128 + tx] = mx1; red[256 + tx] = mx2; }
    __syncthreads();
    if (ty == 0) {
        mx0 = fmaxf(mx0, red[tx]);
        mx1 = fmaxf(mx1, red[128 + tx]);
        mx2 = fmaxf(mx2, red[256 + tx]);
        int c = ct * 128 + tx;
        out[((size_t)(g * 3 + 0) * 30 + p) * SUMH + c] = mx0 + cb[0];
        out[((size_t)(g * 3 + 1) * 30 + p) * SUMH + c] = mx1 + cb[1];
        out[((size_t)(g * 3 + 2) * 30 + p) * SUMH + c] = mx2 + cb[2];
    }
}

// ---------------- driver ----------------
extern "C" void kernel_launch(void* const* d_in, const int* in_sizes, int n_in,
                              void* d_out, int out_size) {
    const float* feat = (const float*)d_in[0];
    const int*   src  = (const int*)d_in[1];
    const int*   dst  = (const int*)d_in[2];
    const float* W1 = (const float*)d_in[3];  const float* b1 = (const float*)d_in[4];
    const float* W2 = (const float*)d_in[5];  const float* b2 = (const float*)d_in[6];
    const float* W3 = (const float*)d_in[7];  const float* b3 = (const float*)d_in[8];
    const float* W4 = (const float*)d_in[9];  const float* b4 = (const float*)d_in[10];
    const float* cw = (const float*)d_in[11]; const float* cb = (const float*)d_in[12];
    float* out = (float*)d_out;

    build_csr_kernel<<<Gn, 256>>>(src, dst);

    // layer 1: input = features (K=128): 8 nodes/CTA
    spmm_kernel<128, false><<<dim3(NN / 8, Gn), 256>>>(feat, 0);
    gemm_kernel<128><<<dim3(10, 2, Gn), 256>>>(W1, b1, 0);
    // layer 2
    spmm_kernel<256, true><<<dim3(NN / 4, Gn), 256>>>(nullptr, 0);
    gemm_kernel<256><<<dim3(10, 2, Gn), 256>>>(W2, b2, 256);
    // layer 3
    spmm_kernel<256, true><<<dim3(NN / 4, Gn), 256>>>(nullptr, 256);
    gemm_kernel<256><<<dim3(10, 2, Gn), 256>>>(W3, b3, 512);
    // layer 4
    spmm_kernel<256, true><<<dim3(NN / 4, Gn), 256>>>(nullptr, 512);
    gemm_kernel<256><<<dim3(10, 2, Gn), 256>>>(W4, b4, 768);

    conv_pool_kernel<<<dim3(8, 30, Gn), 256>>>(cw, cb, out);
}